// round 6
// baseline (speedup 1.0000x reference)
#include <cuda_runtime.h>
#include <cuda_bf16.h>
#include <cstdint>

// Problem dims
#define BDIM 32
#define CDIM 256
#define FDIM 2048
constexpr int NTOT = BDIM * CDIM * FDIM;          // 16,777,216
constexpr int G1 = 2048;                           // kernel1 grid
constexpr int T1 = 256;                            // kernel1 block
constexpr int NPAIR = 10;                          // 4x4 tile pairs (ti<=tj)
constexpr int G2 = BDIM * NPAIR;                   // 320 gemm blocks

// Scratch (device globals: allocation-free). s8-quantized cos/sin (x127).
__device__ __align__(16) signed char g_c[NTOT];
__device__ __align__(16) signed char g_s[NTOT];
__device__ float g_magp[G1];
__device__ float g_php[G1];
__device__ float g_cohp[G2];

__constant__ int c_pi[NPAIR] = {0,0,0,0,1,1,1,2,2,3};
__constant__ int c_pj[NPAIR] = {0,1,2,3,1,2,3,2,3,3};

// ---------------------------------------------------------------------------
// Kernel 1: elementwise losses + s8 cos/sin scratch (HBM-bound)
// ---------------------------------------------------------------------------
__device__ __forceinline__ unsigned pack4(float a, float b, float c, float d) {
    int q0 = __float2int_rn(a * 127.f);
    int q1 = __float2int_rn(b * 127.f);
    int q2 = __float2int_rn(c * 127.f);
    int q3 = __float2int_rn(d * 127.f);
    return (q0 & 255) | ((q1 & 255) << 8) | ((q2 & 255) << 16) | ((q3 & 255) << 24);
}

__global__ void __launch_bounds__(T1) k_elem(
    const float4* __restrict__ mh, const float4* __restrict__ ph,
    const float4* __restrict__ mt, const float4* __restrict__ pt)
{
    int tid = blockIdx.x * T1 + threadIdx.x;
    const int stride = G1 * T1;                    // float4 stride
    float sm = 0.f, sp = 0.f;
    unsigned* gc = reinterpret_cast<unsigned*>(g_c);
    unsigned* gs = reinterpret_cast<unsigned*>(g_s);
#pragma unroll
    for (int i = 0; i < 8; i++) {
        int idx = tid + i * stride;
        float4 a = mh[idx], b = mt[idx];
        float d0 = a.x - b.x, d1 = a.y - b.y, d2 = a.z - b.z, d3 = a.w - b.w;
        sm += d0 * d0 + d1 * d1 + d2 * d2 + d3 * d3;
        float4 p = ph[idx], q = pt[idx];
        sp += 4.f - __cosf(p.x - q.x) - __cosf(p.y - q.y)
                  - __cosf(p.z - q.z) - __cosf(p.w - q.w);
        float s0, c0, s1, c1, s2, c2, s3, c3;
        __sincosf(p.x, &s0, &c0); __sincosf(p.y, &s1, &c1);
        __sincosf(p.z, &s2, &c2); __sincosf(p.w, &s3, &c3);
        gc[idx] = pack4(c0, c1, c2, c3);
        gs[idx] = pack4(s0, s1, s2, s3);
    }
#pragma unroll
    for (int o = 16; o; o >>= 1) {
        sm += __shfl_xor_sync(0xffffffffu, sm, o);
        sp += __shfl_xor_sync(0xffffffffu, sp, o);
    }
    __shared__ float rm[8], rp[8];
    int w = threadIdx.x >> 5;
    if ((threadIdx.x & 31) == 0) { rm[w] = sm; rp[w] = sp; }
    __syncthreads();
    if (threadIdx.x == 0) {
        float a = 0.f, b = 0.f;
#pragma unroll
        for (int i = 0; i < 8; i++) { a += rm[i]; b += rp[i]; }
        g_magp[blockIdx.x] = a;
        g_php[blockIdx.x] = b;
    }
}

// ---------------------------------------------------------------------------
// Kernel 2: symmetric-pair batched GEMM (s8 IMMA m16n8k32 + ldmatrix)
//   2x2 warp grid, each warp owns a 32x32 sub-tile of the 64x64 block tile.
//   accR  = C_I C_Jt + S_I S_Jt  (real * 127^2 * F, exact int32)
//   accM1 = C_I S_Jt ; accM2 = C_J S_It
//   imag_{I+r,J+c} = accM2[c][r] - accM1[r][c]
// ---------------------------------------------------------------------------
#define KC 64                                      // s8 elems (=bytes) per chunk
#define TILE 64
#define ROWB 80                                    // bytes per smem row (64 + 16 pad)
#define TILEBYTES (TILE * ROWB)                    // 5120
#define STAGEBYTES (4 * TILEBYTES)                 // 20480

__device__ __forceinline__ void cp_async16(void* smem, const void* gmem) {
    unsigned s = (unsigned)__cvta_generic_to_shared(smem);
    asm volatile("cp.async.cg.shared.global [%0], [%1], 16;\n" :: "r"(s), "l"(gmem));
}
#define CP_COMMIT asm volatile("cp.async.commit_group;\n" ::: "memory")
#define CP_WAIT1  asm volatile("cp.async.wait_group 1;\n" ::: "memory")

__device__ __forceinline__ void ldsm_x4(unsigned* r, const void* p) {
    unsigned a = (unsigned)__cvta_generic_to_shared(p);
    asm volatile("ldmatrix.sync.aligned.m8n8.x4.shared.b16 {%0,%1,%2,%3}, [%4];"
        : "=r"(r[0]), "=r"(r[1]), "=r"(r[2]), "=r"(r[3]) : "r"(a));
}

__device__ __forceinline__ void mma_s8(int* d, const unsigned* a, const unsigned* b) {
    asm volatile(
        "mma.sync.aligned.m16n8k32.row.col.s32.s8.s8.s32 "
        "{%0,%1,%2,%3}, {%4,%5,%6,%7}, {%8,%9}, {%0,%1,%2,%3};\n"
        : "+r"(d[0]), "+r"(d[1]), "+r"(d[2]), "+r"(d[3])
        : "r"(a[0]), "r"(a[1]), "r"(a[2]), "r"(a[3]), "r"(b[0]), "r"(b[1]));
}

// A fragment 16x32B: grp0 rows m+0..7 @k0-15, grp1 rows m+8..15 @k0-15,
//   grp2 rows m+0..7 @k16-31, grp3 rows m+8..15 @k16-31 -> a0..a3
__device__ __forceinline__ const void* addrA(const char* T, int r0,
                                             int m, int ksB, int lane) {
    int grp = lane >> 3, lo = lane & 7;
    int row = r0 + m * 16 + ((grp & 1) ? 8 : 0) + lo;
    int colB = ksB + ((grp >> 1) ? 16 : 0);
    return T + row * ROWB + colB;
}
// B fragments, 2 n-tiles: grp0 n+0..7 @k0-15, grp1 n+0..7 @k16-31,
//   grp2 n+8..15 @k0-15, grp3 n+8..15 @k16-31 -> {b(n0)lo,b(n0)hi,b(n1)lo,b(n1)hi}
__device__ __forceinline__ const void* addrB(const char* T, int c0,
                                             int np, int ksB, int lane) {
    int grp = lane >> 3, lo = lane & 7;
    int row = c0 + np * 16 + ((grp >> 1) ? 8 : 0) + lo;
    int colB = ksB + ((grp & 1) ? 16 : 0);
    return T + row * ROWB + colB;
}

__device__ __forceinline__ void load_chunk(size_t boff, int I, int J, int kc,
                                           int stage, int tid, char* raw) {
    const int k0 = kc * KC;
#pragma unroll
    for (int i = 0; i < 8; i++) {
        int e = tid + i * 128;                     // 0..1023
        int t = e >> 8;                            // tile: 0=cI 1=sI 2=cJ 3=sJ
        int q = e & 255;
        int row = q >> 2;
        int cp = q & 3;                            // 16B chunk within 64B row
        const signed char* gsrc = (t & 1) ? g_s : g_c;
        int grow = ((t < 2) ? I : J) + row;
        const signed char* src = gsrc + boff + (size_t)grow * FDIM + k0 + cp * 16;
        char* dst = raw + stage * STAGEBYTES + t * TILEBYTES + row * ROWB + cp * 16;
        cp_async16(dst, src);
    }
}

__global__ void __launch_bounds__(128, 3) k_gemm(const float* __restrict__ tgt_all) {
    __shared__ __align__(16) char raw[2 * STAGEBYTES];   // 40960B; reused in epilogue
    __shared__ float red[4];
    const int bid = blockIdx.x;
    const int b = bid / NPAIR, p = bid % NPAIR;
    const int ti = c_pi[p], tj = c_pj[p];
    const bool diag = (ti == tj);
    const int I = ti * TILE, J = tj * TILE;
    const int tid = threadIdx.x;
    const int w = tid >> 5, lane = tid & 31, g = lane >> 2, t4 = lane & 3;
    const int r0 = (w >> 1) * 32;                  // warp-row base (M)
    const int c0 = (w & 1) * 32;                   // warp-col base (N)
    const size_t boff = (size_t)b * CDIM * FDIM;

    int accR[2][4][4] = {}, accM1[2][4][4] = {}, accM2[2][4][4] = {};

    load_chunk(boff, I, J, 0, 0, tid, raw);
    CP_COMMIT;

    const int NK = FDIM / KC;                      // 32
    for (int kc = 0; kc < NK; kc++) {
        if (kc + 1 < NK) load_chunk(boff, I, J, kc + 1, (kc + 1) & 1, tid, raw);
        CP_COMMIT;
        CP_WAIT1;
        __syncthreads();
        const char* tb = raw + (kc & 1) * STAGEBYTES;
        const char* tCI = tb;
        const char* tSI = tb + TILEBYTES;
        const char* tCJ = tb + 2 * TILEBYTES;
        const char* tSJ = tb + 3 * TILEBYTES;
#pragma unroll
        for (int ks = 0; ks < 2; ks++) {
            const int ksB = ks * 32;
            unsigned aCI[2][4], aSI[2][4], aCJ[2][4];
#pragma unroll
            for (int m = 0; m < 2; m++) {
                ldsm_x4(aCI[m], addrA(tCI, r0, m, ksB, lane));
                ldsm_x4(aSI[m], addrA(tSI, r0, m, ksB, lane));
                if (!diag) ldsm_x4(aCJ[m], addrA(tCJ, r0, m, ksB, lane));
            }
#pragma unroll
            for (int np = 0; np < 2; np++) {
                unsigned bCJ[4], bSJ[4], bSI[4];
                ldsm_x4(bCJ, addrB(tCJ, c0, np, ksB, lane));
                ldsm_x4(bSJ, addrB(tSJ, c0, np, ksB, lane));
                if (!diag) ldsm_x4(bSI, addrB(tSI, c0, np, ksB, lane));
#pragma unroll
                for (int m = 0; m < 2; m++)
#pragma unroll
                    for (int nn = 0; nn < 2; nn++) {
                        int n = np * 2 + nn;
                        mma_s8(accR[m][n], aCI[m], bCJ + 2 * nn);
                        mma_s8(accR[m][n], aSI[m], bSJ + 2 * nn);
                        mma_s8(accM1[m][n], aCI[m], bSJ + 2 * nn);
                        if (!diag) mma_s8(accM2[m][n], aCJ[m], bSI + 2 * nn);
                    }
            }
        }
        __syncthreads();
    }

    // Epilogue: stage M2 (or M1 if diagonal) for transposed read
    int (*Ms)[TILE + 1] = reinterpret_cast<int(*)[TILE + 1]>(raw);
#pragma unroll
    for (int m = 0; m < 2; m++)
#pragma unroll
        for (int n = 0; n < 4; n++)
#pragma unroll
            for (int e = 0; e < 4; e++) {
                int lr = r0 + m * 16 + g + ((e & 2) ? 8 : 0);
                int lc = c0 + n * 8 + 2 * t4 + (e & 1);
                Ms[lr][lc] = diag ? accM1[m][n][e] : accM2[m][n][e];
            }
    __syncthreads();

    const float invF = 1.0f / (127.f * 127.f * (float)FDIM);
    const float* tgt = tgt_all + (size_t)b * CDIM * CDIM;
    float lsum = 0.f;
#pragma unroll
    for (int m = 0; m < 2; m++)
#pragma unroll
        for (int n = 0; n < 4; n++)
#pragma unroll
            for (int e = 0; e < 4; e++) {
                int lr = r0 + m * 16 + g + ((e & 2) ? 8 : 0);
                int lc = c0 + n * 8 + 2 * t4 + (e & 1);
                float real = (float)accR[m][n][e] * invF;
                float imag = (float)(Ms[lc][lr] - accM1[m][n][e]) * invF;
                float pci = sqrtf(fmaf(real, real, fmaf(imag, imag, 1e-8f)));
                float d1 = pci - tgt[(I + lr) * CDIM + (J + lc)];
                lsum = fmaf(d1, d1, lsum);
                if (!diag) {
                    float d2 = pci - tgt[(J + lc) * CDIM + (I + lr)];
                    lsum = fmaf(d2, d2, lsum);
                }
            }
#pragma unroll
    for (int o = 16; o; o >>= 1) lsum += __shfl_xor_sync(0xffffffffu, lsum, o);
    if (lane == 0) red[w] = lsum;
    __syncthreads();
    if (tid == 0) g_cohp[bid] = red[0] + red[1] + red[2] + red[3];
}

// ---------------------------------------------------------------------------
// Kernel 3: combine partials -> (total, mag_loss, phase_loss, coh_loss)
// ---------------------------------------------------------------------------
__global__ void __launch_bounds__(256) k_final(float* __restrict__ out) {
    __shared__ float sm[256], sp[256], sc[256];
    int t = threadIdx.x;
    float m = 0.f, p = 0.f, c = 0.f;
    for (int i = t; i < G1; i += 256) { m += g_magp[i]; p += g_php[i]; }
    for (int i = t; i < G2; i += 256) c += g_cohp[i];
    sm[t] = m; sp[t] = p; sc[t] = c;
    __syncthreads();
    for (int o = 128; o; o >>= 1) {
        if (t < o) { sm[t] += sm[t + o]; sp[t] += sp[t + o]; sc[t] += sc[t + o]; }
        __syncthreads();
    }
    if (t == 0) {
        const float N1 = (float)NTOT;
        const float N2 = (float)(BDIM * CDIM * CDIM);
        float mag = sm[0] / N1;
        float ph  = sp[0] / N1;
        float coh = sc[0] / N2;
        out[0] = 1.0f * mag + 0.5f * ph + 0.3f * coh;
        out[1] = mag;
        out[2] = ph;
        out[3] = coh;
    }
}

// ---------------------------------------------------------------------------
extern "C" void kernel_launch(void* const* d_in, const int* in_sizes, int n_in,
                              void* d_out, int out_size) {
    const float4* mh = (const float4*)d_in[0];   // mag_hat
    const float4* ph = (const float4*)d_in[1];   // phase_hat
    const float4* mt = (const float4*)d_in[2];   // mag_target
    const float4* pt = (const float4*)d_in[3];   // phase_target
    const float*  pc = (const float*)d_in[4];    // pci_target
    float* out = (float*)d_out;

    k_elem<<<G1, T1>>>(mh, ph, mt, pt);
    k_gemm<<<G2, 128>>>(pc);
    k_final<<<1, 256>>>(out);
}

// round 7
// speedup vs baseline: 1.4923x; 1.4923x over previous
#include <cuda_runtime.h>
#include <cuda_bf16.h>
#include <cstdint>

// Problem dims
#define BDIM 32
#define CDIM 256
#define FDIM 2048
constexpr int NTOT = BDIM * CDIM * FDIM;          // 16,777,216
constexpr int N4 = NTOT / 4;                       // 4,194,304 float4s
constexpr int G1 = 2048;                           // k_phase grid
constexpr int T1 = 256;                            // k_phase block
constexpr int NPAIR = 10;                          // 4x4 tile pairs (ti<=tj)
constexpr int G2 = BDIM * NPAIR;                   // 320 gemm blocks
constexpr int MAGSTEP = G2 * 128;                  // 40960 float4 grid stride

// Scratch (device globals: allocation-free)
__device__ __nv_bfloat16 g_c[NTOT];                // cos(phase_hat)
__device__ __nv_bfloat16 g_s[NTOT];                // sin(phase_hat)
__device__ __nv_bfloat16 g_cs[NTOT];               // cos+sin
__device__ float g_php[G1];
__device__ float g_magp[G2];
__device__ float g_cohp[G2];

__constant__ int c_pi[NPAIR] = {0,0,0,0,1,1,1,2,2,3};
__constant__ int c_pj[NPAIR] = {0,1,2,3,1,2,3,2,3,3};

// ---------------------------------------------------------------------------
// Kernel 1: phase loss + cos/sin/(cos+sin) bf16 scratch (HBM-bound)
// ---------------------------------------------------------------------------
__global__ void __launch_bounds__(T1) k_phase(
    const float4* __restrict__ ph, const float4* __restrict__ pt)
{
    int tid = blockIdx.x * T1 + threadIdx.x;
    const int stride = G1 * T1;
    float sp = 0.f;
    uint2* gc = reinterpret_cast<uint2*>(g_c);
    uint2* gs = reinterpret_cast<uint2*>(g_s);
    uint2* gx = reinterpret_cast<uint2*>(g_cs);
#pragma unroll
    for (int i = 0; i < 8; i++) {
        int idx = tid + i * stride;
        float4 p = ph[idx], q = pt[idx];
        sp += 4.f - __cosf(p.x - q.x) - __cosf(p.y - q.y)
                  - __cosf(p.z - q.z) - __cosf(p.w - q.w);
        float s0, c0, s1, c1, s2, c2, s3, c3;
        __sincosf(p.x, &s0, &c0); __sincosf(p.y, &s1, &c1);
        __sincosf(p.z, &s2, &c2); __sincosf(p.w, &s3, &c3);
        __nv_bfloat162 hc0 = __floats2bfloat162_rn(c0, c1);
        __nv_bfloat162 hc1 = __floats2bfloat162_rn(c2, c3);
        __nv_bfloat162 hs0 = __floats2bfloat162_rn(s0, s1);
        __nv_bfloat162 hs1 = __floats2bfloat162_rn(s2, s3);
        __nv_bfloat162 hx0 = __floats2bfloat162_rn(c0 + s0, c1 + s1);
        __nv_bfloat162 hx1 = __floats2bfloat162_rn(c2 + s2, c3 + s3);
        gc[idx] = make_uint2(*reinterpret_cast<unsigned*>(&hc0),
                             *reinterpret_cast<unsigned*>(&hc1));
        gs[idx] = make_uint2(*reinterpret_cast<unsigned*>(&hs0),
                             *reinterpret_cast<unsigned*>(&hs1));
        gx[idx] = make_uint2(*reinterpret_cast<unsigned*>(&hx0),
                             *reinterpret_cast<unsigned*>(&hx1));
    }
#pragma unroll
    for (int o = 16; o; o >>= 1) sp += __shfl_xor_sync(0xffffffffu, sp, o);
    __shared__ float rp[8];
    int w = threadIdx.x >> 5;
    if ((threadIdx.x & 31) == 0) rp[w] = sp;
    __syncthreads();
    if (threadIdx.x == 0) {
        float b = 0.f;
#pragma unroll
        for (int i = 0; i < 8; i++) b += rp[i];
        g_php[blockIdx.x] = b;
    }
}

// ---------------------------------------------------------------------------
// Kernel 2: Gauss 3-mult symmetric-pair batched GEMM (bf16 mma.sync)
//   m1 = (C_I+S_I)(C_J+S_J)^T, m2 = C_I S_J^T, m3 = S_I C_J^T
//   real = (m1 - m2 - m3)/F ; imag = (m3 - m2)/F
//   diag (I==J): m3(r,c) = m2(c,r) -> smem transpose, only m1,m2 streams.
//   Also folds mag-MSE partial loads under the MMA pipeline.
// ---------------------------------------------------------------------------
#define KC 32
#define TILE 64
#define ROWSTRIDE 40                               // bf16 elems per smem row (pad 8)
#define TILEBYTES (TILE * ROWSTRIDE * 2)           // 5120
#define STAGEBYTES (6 * TILEBYTES)                 // 30720 (CS_I,C_I,S_I,CS_J,C_J,S_J)
#define SMEM_DYN (2 * STAGEBYTES)                  // 61440

__device__ __forceinline__ void cp_async16(void* smem, const void* gmem) {
    unsigned s = (unsigned)__cvta_generic_to_shared(smem);
    asm volatile("cp.async.cg.shared.global [%0], [%1], 16;\n" :: "r"(s), "l"(gmem));
}
#define CP_COMMIT asm volatile("cp.async.commit_group;\n" ::: "memory")
#define CP_WAIT1  asm volatile("cp.async.wait_group 1;\n" ::: "memory")

__device__ __forceinline__ void ldsm_x4(unsigned* r, const void* p) {
    unsigned a = (unsigned)__cvta_generic_to_shared(p);
    asm volatile("ldmatrix.sync.aligned.m8n8.x4.shared.b16 {%0,%1,%2,%3}, [%4];"
        : "=r"(r[0]), "=r"(r[1]), "=r"(r[2]), "=r"(r[3]) : "r"(a));
}

__device__ __forceinline__ void mma_bf16(float* d, const unsigned* a, const unsigned* b) {
    asm volatile(
        "mma.sync.aligned.m16n8k16.row.col.f32.bf16.bf16.f32 "
        "{%0,%1,%2,%3}, {%4,%5,%6,%7}, {%8,%9}, {%0,%1,%2,%3};\n"
        : "+f"(d[0]), "+f"(d[1]), "+f"(d[2]), "+f"(d[3])
        : "r"(a[0]), "r"(a[1]), "r"(a[2]), "r"(a[3]), "r"(b[0]), "r"(b[1]));
}

__device__ __forceinline__ const void* addrA(const __nv_bfloat16* T, int r0,
                                             int m, int k0, int lane) {
    int grp = lane >> 3, lo = lane & 7;
    int row = r0 + m * 16 + ((grp & 1) ? 8 : 0) + lo;
    int col = k0 + ((grp >> 1) ? 8 : 0);
    return T + row * ROWSTRIDE + col;
}
__device__ __forceinline__ const void* addrB(const __nv_bfloat16* T, int c0,
                                             int np, int k0, int lane) {
    int grp = lane >> 3, lo = lane & 7;
    int row = c0 + np * 16 + ((grp >> 1) ? 8 : 0) + lo;
    int col = k0 + ((grp & 1) ? 8 : 0);
    return T + row * ROWSTRIDE + col;
}

__device__ __forceinline__ void load_chunk(size_t boff, int I, int J, int kc,
                                           int stage, int tid, char* raw, int ntile) {
    const int k0 = kc * KC;
#pragma unroll
    for (int i = 0; i < 12; i++) {                 // up to 6 tiles * 256 elems /128 thr
        int e = tid + i * 128;
        int t = e >> 8;                            // tile 0..5
        if (t >= ntile) break;
        int q = e & 255;
        int row = q >> 2;
        int cp = q & 3;                            // 16B chunk within 64B row
        int sel = (t >= 3) ? t - 3 : t;            // 0=CS 1=C 2=S
        const __nv_bfloat16* gsrc = (sel == 0) ? g_cs : (sel == 1) ? g_c : g_s;
        int grow = ((t < 3) ? I : J) + row;
        const __nv_bfloat16* src = gsrc + boff + (size_t)grow * FDIM + k0 + cp * 8;
        char* dst = raw + stage * STAGEBYTES + t * TILEBYTES + row * (ROWSTRIDE * 2) + cp * 16;
        cp_async16(dst, src);
    }
}

extern __shared__ char dynraw[];

__global__ void __launch_bounds__(128) k_gemm(
    const float* __restrict__ tgt_all,
    const float4* __restrict__ mh, const float4* __restrict__ mt)
{
    __shared__ float red[4], redm[4];
    char* raw = dynraw;
    const int bid = blockIdx.x;
    const int b = bid / NPAIR, p = bid % NPAIR;
    const int ti = c_pi[p], tj = c_pj[p];
    const bool diag = (ti == tj);
    const int I = ti * TILE, J = tj * TILE;
    const int tid = threadIdx.x;
    const int w = tid >> 5, lane = tid & 31, g = lane >> 2, t4 = lane & 3;
    const int r0 = (w >> 1) * 32;                  // warp-row base (M)
    const int c0 = (w & 1) * 32;                   // warp-col base (N)
    const size_t boff = (size_t)b * CDIM * FDIM;
    const int ntile = diag ? 3 : 6;
    const int magbase = bid * 128 + tid;           // float4 index base for mag MSE

    float m1[2][4][4] = {}, m2[2][4][4] = {}, m3[2][4][4] = {};
    float msum = 0.f;

    load_chunk(boff, I, J, 0, 0, tid, raw, ntile);
    CP_COMMIT;

    const int NK = FDIM / KC;                      // 64
    for (int kc = 0; kc < NK; kc++) {
        if (kc + 1 < NK) load_chunk(boff, I, J, kc + 1, (kc + 1) & 1, tid, raw, ntile);
        CP_COMMIT;
        // mag MSE loads ride under the pipeline (2 slots/chunk -> 128 >= 103 iters)
#pragma unroll
        for (int u = 0; u < 2; u++) {
            int it = kc * 2 + u;
            int idx = magbase + it * MAGSTEP;
            if (idx < N4) {
                float4 a = mh[idx], c = mt[idx];
                float d0 = a.x - c.x, d1 = a.y - c.y, d2 = a.z - c.z, d3 = a.w - c.w;
                msum += d0 * d0 + d1 * d1 + d2 * d2 + d3 * d3;
            }
        }
        CP_WAIT1;
        __syncthreads();
        const __nv_bfloat16* tb = reinterpret_cast<const __nv_bfloat16*>(raw + (kc & 1) * STAGEBYTES);
        const __nv_bfloat16* tCSI = tb;
        const __nv_bfloat16* tCI  = tb + TILEBYTES / 2;
        const __nv_bfloat16* tSI  = tb + TILEBYTES;
        const __nv_bfloat16* tCSJ = diag ? tCSI : tb + 3 * TILEBYTES / 2;
        const __nv_bfloat16* tCJ  = diag ? tCI  : tb + 2 * TILEBYTES;
        const __nv_bfloat16* tSJ  = diag ? tSI  : tb + 5 * TILEBYTES / 2;
#pragma unroll
        for (int ks = 0; ks < 2; ks++) {
            const int k0 = ks * 16;
            unsigned aCS[2][4], aC[2][4], aS[2][4];
#pragma unroll
            for (int m = 0; m < 2; m++) {
                ldsm_x4(aCS[m], addrA(tCSI, r0, m, k0, lane));
                ldsm_x4(aC[m], addrA(tCI, r0, m, k0, lane));
                if (!diag) ldsm_x4(aS[m], addrA(tSI, r0, m, k0, lane));
            }
#pragma unroll
            for (int np = 0; np < 2; np++) {
                unsigned bCS[4], bS[4], bC[4];
                ldsm_x4(bCS, addrB(tCSJ, c0, np, k0, lane));
                ldsm_x4(bS, addrB(tSJ, c0, np, k0, lane));
                if (!diag) ldsm_x4(bC, addrB(tCJ, c0, np, k0, lane));
#pragma unroll
                for (int m = 0; m < 2; m++)
#pragma unroll
                    for (int nn = 0; nn < 2; nn++) {
                        int n = np * 2 + nn;
                        mma_bf16(m1[m][n], aCS[m], bCS + 2 * nn);
                        mma_bf16(m2[m][n], aC[m], bS + 2 * nn);
                        if (!diag) mma_bf16(m3[m][n], aS[m], bC + 2 * nn);
                    }
            }
        }
        __syncthreads();
    }

    // Diag: stage m2 for transposed read (m3(r,c) = m2(c,r))
    float (*Ms)[TILE + 1] = reinterpret_cast<float(*)[TILE + 1]>(raw);
    if (diag) {
#pragma unroll
        for (int m = 0; m < 2; m++)
#pragma unroll
            for (int n = 0; n < 4; n++)
#pragma unroll
                for (int e = 0; e < 4; e++) {
                    int lr = r0 + m * 16 + g + ((e & 2) ? 8 : 0);
                    int lc = c0 + n * 8 + 2 * t4 + (e & 1);
                    Ms[lr][lc] = m2[m][n][e];
                }
    }
    __syncthreads();

    const float invF = 1.0f / (float)FDIM;
    const float* tgt = tgt_all + (size_t)b * CDIM * CDIM;
    float lsum = 0.f;
#pragma unroll
    for (int m = 0; m < 2; m++)
#pragma unroll
        for (int n = 0; n < 4; n++)
#pragma unroll
            for (int e = 0; e < 4; e++) {
                int lr = r0 + m * 16 + g + ((e & 2) ? 8 : 0);
                int lc = c0 + n * 8 + 2 * t4 + (e & 1);
                float v2 = m2[m][n][e];
                float v3 = diag ? Ms[lc][lr] : m3[m][n][e];
                float real = (m1[m][n][e] - v2 - v3) * invF;
                float imag = (v3 - v2) * invF;
                float pci = sqrtf(fmaf(real, real, fmaf(imag, imag, 1e-8f)));
                float d1 = pci - tgt[(I + lr) * CDIM + (J + lc)];
                lsum = fmaf(d1, d1, lsum);
                if (!diag) {
                    float d2 = pci - tgt[(J + lc) * CDIM + (I + lr)];
                    lsum = fmaf(d2, d2, lsum);
                }
            }
#pragma unroll
    for (int o = 16; o; o >>= 1) {
        lsum += __shfl_xor_sync(0xffffffffu, lsum, o);
        msum += __shfl_xor_sync(0xffffffffu, msum, o);
    }
    if (lane == 0) { red[w] = lsum; redm[w] = msum; }
    __syncthreads();
    if (tid == 0) {
        g_cohp[bid] = red[0] + red[1] + red[2] + red[3];
        g_magp[bid] = redm[0] + redm[1] + redm[2] + redm[3];
    }
}

// ---------------------------------------------------------------------------
// Kernel 3: combine partials -> (total, mag_loss, phase_loss, coh_loss)
// ---------------------------------------------------------------------------
__global__ void __launch_bounds__(256) k_final(float* __restrict__ out) {
    __shared__ float sm[256], sp[256], sc[256];
    int t = threadIdx.x;
    float m = 0.f, p = 0.f, c = 0.f;
    for (int i = t; i < G1; i += 256) p += g_php[i];
    for (int i = t; i < G2; i += 256) { m += g_magp[i]; c += g_cohp[i]; }
    sm[t] = m; sp[t] = p; sc[t] = c;
    __syncthreads();
    for (int o = 128; o; o >>= 1) {
        if (t < o) { sm[t] += sm[t + o]; sp[t] += sp[t + o]; sc[t] += sc[t + o]; }
        __syncthreads();
    }
    if (t == 0) {
        const float N1 = (float)NTOT;
        const float N2 = (float)(BDIM * CDIM * CDIM);
        float mag = sm[0] / N1;
        float ph  = sp[0] / N1;
        float coh = sc[0] / N2;
        out[0] = 1.0f * mag + 0.5f * ph + 0.3f * coh;
        out[1] = mag;
        out[2] = ph;
        out[3] = coh;
    }
}

// ---------------------------------------------------------------------------
extern "C" void kernel_launch(void* const* d_in, const int* in_sizes, int n_in,
                              void* d_out, int out_size) {
    const float4* mh = (const float4*)d_in[0];   // mag_hat
    const float4* ph = (const float4*)d_in[1];   // phase_hat
    const float4* mt = (const float4*)d_in[2];   // mag_target
    const float4* pt = (const float4*)d_in[3];   // phase_target
    const float*  pc = (const float*)d_in[4];    // pci_target
    float* out = (float*)d_out;

    static bool attr_set = false;
    if (!attr_set) {
        cudaFuncSetAttribute(k_gemm, cudaFuncAttributeMaxDynamicSharedMemorySize, SMEM_DYN);
        attr_set = true;
    }

    k_phase<<<G1, T1>>>(ph, pt);
    k_gemm<<<G2, 128, SMEM_DYN>>>(pc, mh, mt);
    k_final<<<1, 256>>>(out);
}

// round 8
// speedup vs baseline: 1.9707x; 1.3206x over previous
#include <cuda_runtime.h>
#include <cuda_bf16.h>
#include <cstdint>

// Problem dims
#define BDIM 32
#define CDIM 256
#define FDIM 2048
constexpr int NTOT = BDIM * CDIM * FDIM;          // 16,777,216
constexpr int G1 = 2048;                           // kernel1 grid
constexpr int T1 = 256;                            // kernel1 block
constexpr int NPAIR = 10;                          // 4x4 tile pairs (ti<=tj)
constexpr int G2 = BDIM * NPAIR;                   // 320 gemm blocks

// Scratch (device globals: allocation-free)
__device__ __nv_bfloat16 g_c[NTOT];                // cos(phase_hat) bf16
__device__ __nv_bfloat16 g_s[NTOT];                // sin(phase_hat) bf16
__device__ float g_magp[G1];
__device__ float g_php[G1];
__device__ float g_cohp[G2];

__constant__ int c_pi[NPAIR] = {0,0,0,0,1,1,1,2,2,3};
__constant__ int c_pj[NPAIR] = {0,1,2,3,1,2,3,2,3,3};

// ---------------------------------------------------------------------------
// Kernel 1: elementwise losses + cos/sin scratch (HBM-bound, round-2 proven)
// ---------------------------------------------------------------------------
__global__ void __launch_bounds__(T1) k_elem(
    const float4* __restrict__ mh, const float4* __restrict__ ph,
    const float4* __restrict__ mt, const float4* __restrict__ pt)
{
    int tid = blockIdx.x * T1 + threadIdx.x;
    const int stride = G1 * T1;                    // float4 stride
    float sm = 0.f, sp = 0.f;
    uint2* gc = reinterpret_cast<uint2*>(g_c);
    uint2* gs = reinterpret_cast<uint2*>(g_s);
#pragma unroll
    for (int i = 0; i < 8; i++) {
        int idx = tid + i * stride;
        float4 a = mh[idx], b = mt[idx];
        float d0 = a.x - b.x, d1 = a.y - b.y, d2 = a.z - b.z, d3 = a.w - b.w;
        sm += d0 * d0 + d1 * d1 + d2 * d2 + d3 * d3;
        float4 p = ph[idx], q = pt[idx];
        sp += 4.f - __cosf(p.x - q.x) - __cosf(p.y - q.y)
                  - __cosf(p.z - q.z) - __cosf(p.w - q.w);
        float s0, c0, s1, c1, s2, c2, s3, c3;
        __sincosf(p.x, &s0, &c0); __sincosf(p.y, &s1, &c1);
        __sincosf(p.z, &s2, &c2); __sincosf(p.w, &s3, &c3);
        __nv_bfloat162 hc0 = __floats2bfloat162_rn(c0, c1);
        __nv_bfloat162 hc1 = __floats2bfloat162_rn(c2, c3);
        __nv_bfloat162 hs0 = __floats2bfloat162_rn(s0, s1);
        __nv_bfloat162 hs1 = __floats2bfloat162_rn(s2, s3);
        gc[idx] = make_uint2(*reinterpret_cast<unsigned*>(&hc0),
                             *reinterpret_cast<unsigned*>(&hc1));
        gs[idx] = make_uint2(*reinterpret_cast<unsigned*>(&hs0),
                             *reinterpret_cast<unsigned*>(&hs1));
    }
#pragma unroll
    for (int o = 16; o; o >>= 1) {
        sm += __shfl_xor_sync(0xffffffffu, sm, o);
        sp += __shfl_xor_sync(0xffffffffu, sp, o);
    }
    __shared__ float rm[8], rp[8];
    int w = threadIdx.x >> 5;
    if ((threadIdx.x & 31) == 0) { rm[w] = sm; rp[w] = sp; }
    __syncthreads();
    if (threadIdx.x == 0) {
        float a = 0.f, b = 0.f;
#pragma unroll
        for (int i = 0; i < 8; i++) { a += rm[i]; b += rp[i]; }
        g_magp[blockIdx.x] = a;
        g_php[blockIdx.x] = b;
    }
}

// ---------------------------------------------------------------------------
// Kernel 2: Gauss 3-mult symmetric-pair batched GEMM (bf16 mma.sync)
//   CS fragments built in registers via HADD2 (no extra memory stream).
//   m1 = (C_I+S_I)(C_J+S_J)^T, m2 = C_I S_J^T, m3 = S_I C_J^T
//   real = (m1 - m2 - m3)/F ; imag = (m3 - m2)/F
//   diag (I==J): m3(r,c) = m2(c,r) via smem transpose -> 2 MMA streams only.
// ---------------------------------------------------------------------------
#define KC 32
#define TILE 64
#define ROWSTRIDE 40                               // bf16 elems per smem row (pad 8)
#define TILEBYTES (TILE * ROWSTRIDE * 2)           // 5120
#define STAGEBYTES (4 * TILEBYTES)                 // 20480

__device__ __forceinline__ void cp_async16(void* smem, const void* gmem) {
    unsigned s = (unsigned)__cvta_generic_to_shared(smem);
    asm volatile("cp.async.cg.shared.global [%0], [%1], 16;\n" :: "r"(s), "l"(gmem));
}
#define CP_COMMIT asm volatile("cp.async.commit_group;\n" ::: "memory")
#define CP_WAIT1  asm volatile("cp.async.wait_group 1;\n" ::: "memory")

__device__ __forceinline__ void ldsm_x4(unsigned* r, const void* p) {
    unsigned a = (unsigned)__cvta_generic_to_shared(p);
    asm volatile("ldmatrix.sync.aligned.m8n8.x4.shared.b16 {%0,%1,%2,%3}, [%4];"
        : "=r"(r[0]), "=r"(r[1]), "=r"(r[2]), "=r"(r[3]) : "r"(a));
}

__device__ __forceinline__ void mma_bf16(float* d, const unsigned* a, const unsigned* b) {
    asm volatile(
        "mma.sync.aligned.m16n8k16.row.col.f32.bf16.bf16.f32 "
        "{%0,%1,%2,%3}, {%4,%5,%6,%7}, {%8,%9}, {%0,%1,%2,%3};\n"
        : "+f"(d[0]), "+f"(d[1]), "+f"(d[2]), "+f"(d[3])
        : "r"(a[0]), "r"(a[1]), "r"(a[2]), "r"(a[3]), "r"(b[0]), "r"(b[1]));
}

__device__ __forceinline__ unsigned hadd2u(unsigned x, unsigned y) {
    __nv_bfloat162 a = *reinterpret_cast<__nv_bfloat162*>(&x);
    __nv_bfloat162 b = *reinterpret_cast<__nv_bfloat162*>(&y);
    __nv_bfloat162 r = __hadd2(a, b);
    return *reinterpret_cast<unsigned*>(&r);
}

__device__ __forceinline__ const void* addrA(const __nv_bfloat16* T, int r0,
                                             int m, int k0, int lane) {
    int grp = lane >> 3, lo = lane & 7;
    int row = r0 + m * 16 + ((grp & 1) ? 8 : 0) + lo;
    int col = k0 + ((grp >> 1) ? 8 : 0);
    return T + row * ROWSTRIDE + col;
}
__device__ __forceinline__ const void* addrB(const __nv_bfloat16* T, int c0,
                                             int np, int k0, int lane) {
    int grp = lane >> 3, lo = lane & 7;
    int row = c0 + np * 16 + ((grp >> 1) ? 8 : 0) + lo;
    int col = k0 + ((grp & 1) ? 8 : 0);
    return T + row * ROWSTRIDE + col;
}

__device__ __forceinline__ void load_chunk(size_t boff, int I, int J, int kc,
                                           int stage, int tid, char* raw) {
    const int k0 = kc * KC;
#pragma unroll
    for (int i = 0; i < 8; i++) {
        int e = tid + i * 128;                     // 0..1023
        int t = e >> 8;                            // tile: 0=cI 1=sI 2=cJ 3=sJ
        int q = e & 255;
        int row = q >> 2;
        int cp = q & 3;                            // 16B chunk within row
        const __nv_bfloat16* gsrc = (t & 1) ? g_s : g_c;
        int grow = ((t < 2) ? I : J) + row;
        const __nv_bfloat16* src = gsrc + boff + (size_t)grow * FDIM + k0 + cp * 8;
        char* dst = raw + stage * STAGEBYTES + t * TILEBYTES + row * (ROWSTRIDE * 2) + cp * 16;
        cp_async16(dst, src);
    }
}

__global__ void __launch_bounds__(128) k_gemm(const float* __restrict__ tgt_all) {
    __shared__ __align__(16) char raw[2 * STAGEBYTES];   // 40960B; reused in epilogue
    __shared__ float red[4];
    const int bid = blockIdx.x;
    const int b = bid / NPAIR, p = bid % NPAIR;
    const int ti = c_pi[p], tj = c_pj[p];
    const bool diag = (ti == tj);
    const int I = ti * TILE, J = tj * TILE;
    const int tid = threadIdx.x;
    const int w = tid >> 5, lane = tid & 31, g = lane >> 2, t4 = lane & 3;
    const int r0 = (w >> 1) * 32;                  // warp-row base (M)
    const int c0 = (w & 1) * 32;                   // warp-col base (N)
    const size_t boff = (size_t)b * CDIM * FDIM;

    float m1[2][4][4] = {}, m2[2][4][4] = {}, m3[2][4][4] = {};

    load_chunk(boff, I, J, 0, 0, tid, raw);
    CP_COMMIT;

    const int NK = FDIM / KC;                      // 64
    for (int kc = 0; kc < NK; kc++) {
        if (kc + 1 < NK) load_chunk(boff, I, J, kc + 1, (kc + 1) & 1, tid, raw);
        CP_COMMIT;
        CP_WAIT1;
        __syncthreads();
        const __nv_bfloat16* tb = reinterpret_cast<const __nv_bfloat16*>(raw + (kc & 1) * STAGEBYTES);
        const __nv_bfloat16* tCI = tb;
        const __nv_bfloat16* tSI = tb + TILEBYTES / 2;
        const __nv_bfloat16* tCJ = tb + TILEBYTES;
        const __nv_bfloat16* tSJ = tb + 3 * TILEBYTES / 2;
#pragma unroll
        for (int ks = 0; ks < 2; ks++) {
            const int k0 = ks * 16;
            unsigned aC[2][4], aS[2][4], aCS[2][4];
#pragma unroll
            for (int m = 0; m < 2; m++) {
                ldsm_x4(aC[m], addrA(tCI, r0, m, k0, lane));
                ldsm_x4(aS[m], addrA(tSI, r0, m, k0, lane));
#pragma unroll
                for (int r = 0; r < 4; r++) aCS[m][r] = hadd2u(aC[m][r], aS[m][r]);
            }
#pragma unroll
            for (int np = 0; np < 2; np++) {
                unsigned bC[4], bS[4], bCS[4];
                ldsm_x4(bS, addrB(tSJ, c0, np, k0, lane));
                ldsm_x4(bC, addrB(tCJ, c0, np, k0, lane));
#pragma unroll
                for (int r = 0; r < 4; r++) bCS[r] = hadd2u(bC[r], bS[r]);
#pragma unroll
                for (int m = 0; m < 2; m++)
#pragma unroll
                    for (int nn = 0; nn < 2; nn++) {
                        int n = np * 2 + nn;
                        mma_bf16(m1[m][n], aCS[m], bCS + 2 * nn);
                        mma_bf16(m2[m][n], aC[m], bS + 2 * nn);
                        if (!diag) mma_bf16(m3[m][n], aS[m], bC + 2 * nn);
                    }
            }
        }
        __syncthreads();
    }

    // Diag: stage m2 for transposed read (m3(r,c) = m2(c,r))
    float (*Ms)[TILE + 1] = reinterpret_cast<float(*)[TILE + 1]>(raw);
    if (diag) {
#pragma unroll
        for (int m = 0; m < 2; m++)
#pragma unroll
            for (int n = 0; n < 4; n++)
#pragma unroll
                for (int e = 0; e < 4; e++) {
                    int lr = r0 + m * 16 + g + ((e & 2) ? 8 : 0);
                    int lc = c0 + n * 8 + 2 * t4 + (e & 1);
                    Ms[lr][lc] = m2[m][n][e];
                }
    }
    __syncthreads();

    const float invF = 1.0f / (float)FDIM;
    const float* tgt = tgt_all + (size_t)b * CDIM * CDIM;
    float lsum = 0.f;
#pragma unroll
    for (int m = 0; m < 2; m++)
#pragma unroll
        for (int n = 0; n < 4; n++)
#pragma unroll
            for (int e = 0; e < 4; e++) {
                int lr = r0 + m * 16 + g + ((e & 2) ? 8 : 0);
                int lc = c0 + n * 8 + 2 * t4 + (e & 1);
                float v2 = m2[m][n][e];
                float v3 = diag ? Ms[lc][lr] : m3[m][n][e];
                float real = (m1[m][n][e] - v2 - v3) * invF;
                float imag = (v3 - v2) * invF;
                float pci = sqrtf(fmaf(real, real, fmaf(imag, imag, 1e-8f)));
                float d1 = pci - tgt[(I + lr) * CDIM + (J + lc)];
                lsum = fmaf(d1, d1, lsum);
                if (!diag) {
                    float d2 = pci - tgt[(J + lc) * CDIM + (I + lr)];
                    lsum = fmaf(d2, d2, lsum);
                }
            }
#pragma unroll
    for (int o = 16; o; o >>= 1) lsum += __shfl_xor_sync(0xffffffffu, lsum, o);
    if (lane == 0) red[w] = lsum;
    __syncthreads();
    if (tid == 0) g_cohp[bid] = red[0] + red[1] + red[2] + red[3];
}

// ---------------------------------------------------------------------------
// Kernel 3: combine partials -> (total, mag_loss, phase_loss, coh_loss)
// ---------------------------------------------------------------------------
__global__ void __launch_bounds__(256) k_final(float* __restrict__ out) {
    __shared__ float sm[256], sp[256], sc[256];
    int t = threadIdx.x;
    float m = 0.f, p = 0.f, c = 0.f;
    for (int i = t; i < G1; i += 256) { m += g_magp[i]; p += g_php[i]; }
    for (int i = t; i < G2; i += 256) c += g_cohp[i];
    sm[t] = m; sp[t] = p; sc[t] = c;
    __syncthreads();
    for (int o = 128; o; o >>= 1) {
        if (t < o) { sm[t] += sm[t + o]; sp[t] += sp[t + o]; sc[t] += sc[t + o]; }
        __syncthreads();
    }
    if (t == 0) {
        const float N1 = (float)NTOT;
        const float N2 = (float)(BDIM * CDIM * CDIM);
        float mag = sm[0] / N1;
        float ph  = sp[0] / N1;
        float coh = sc[0] / N2;
        out[0] = 1.0f * mag + 0.5f * ph + 0.3f * coh;
        out[1] = mag;
        out[2] = ph;
        out[3] = coh;
    }
}

// ---------------------------------------------------------------------------
extern "C" void kernel_launch(void* const* d_in, const int* in_sizes, int n_in,
                              void* d_out, int out_size) {
    const float4* mh = (const float4*)d_in[0];   // mag_hat
    const float4* ph = (const float4*)d_in[1];   // phase_hat
    const float4* mt = (const float4*)d_in[2];   // mag_target
    const float4* pt = (const float4*)d_in[3];   // phase_target
    const float*  pc = (const float*)d_in[4];    // pci_target
    float* out = (float*)d_out;

    k_elem<<<G1, T1>>>(mh, ph, mt, pt);
    k_gemm<<<G2, 128>>>(pc);
    k_final<<<1, 256>>>(out);
}